// round 3
// baseline (speedup 1.0000x reference)
#include <cuda_runtime.h>

// Cross product along dim=1 of (16, 3, 1024, 1024) fp32.
// R3: single-wave persistent grid-stride kernel (148 SMs x 8 CTAs), 6 loads /
// 3 stores per work unit, __ldcs streaming loads, plain stores (R1's best combo).

static constexpr int CH_ELEMS = 1024 * 1024;          // elems per channel plane
static constexpr int CH_VEC   = CH_ELEMS / 4;         // float4 per plane = 2^18
static constexpr int NBATCH   = 16;
static constexpr long TOTAL_U = (long)NBATCH * CH_VEC; // 4,194,304 work units
static constexpr int TPB      = 256;
static constexpr int NSM      = 148;
static constexpr int CTAS_PER_SM = 8;
static constexpr int NCTA     = NSM * CTAS_PER_SM;    // 1184

__global__ __launch_bounds__(TPB, CTAS_PER_SM) void cross_kernel(
    const float4* __restrict__ A,
    const float4* __restrict__ B,
    float4* __restrict__ O)
{
    const long stride = (long)NCTA * TPB;             // 303,104
    for (long u = (long)blockIdx.x * TPB + threadIdx.x; u < TOTAL_U; u += stride) {
        // u = b * CH_VEC + s ; CH_VEC = 2^18 -> shift/mask
        const long b = u >> 18;
        const long s = u & (CH_VEC - 1);
        const long base = b * (3L * CH_VEC) + s;

        const float4 a0 = __ldcs(&A[base]);
        const float4 a1 = __ldcs(&A[base + CH_VEC]);
        const float4 a2 = __ldcs(&A[base + 2 * CH_VEC]);
        const float4 b0 = __ldcs(&B[base]);
        const float4 b1 = __ldcs(&B[base + CH_VEC]);
        const float4 b2 = __ldcs(&B[base + 2 * CH_VEC]);

        float4 c0, c1, c2;
        c0.x = fmaf(a1.x, b2.x, -a2.x * b1.x);
        c0.y = fmaf(a1.y, b2.y, -a2.y * b1.y);
        c0.z = fmaf(a1.z, b2.z, -a2.z * b1.z);
        c0.w = fmaf(a1.w, b2.w, -a2.w * b1.w);

        c1.x = fmaf(a2.x, b0.x, -a0.x * b2.x);
        c1.y = fmaf(a2.y, b0.y, -a0.y * b2.y);
        c1.z = fmaf(a2.z, b0.z, -a0.z * b2.z);
        c1.w = fmaf(a2.w, b0.w, -a0.w * b2.w);

        c2.x = fmaf(a0.x, b1.x, -a1.x * b0.x);
        c2.y = fmaf(a0.y, b1.y, -a1.y * b0.y);
        c2.z = fmaf(a0.z, b1.z, -a1.z * b0.z);
        c2.w = fmaf(a0.w, b1.w, -a1.w * b0.w);

        O[base]              = c0;
        O[base + CH_VEC]     = c1;
        O[base + 2 * CH_VEC] = c2;
    }
}

extern "C" void kernel_launch(void* const* d_in, const int* in_sizes, int n_in,
                              void* d_out, int out_size)
{
    const float4* A = (const float4*)d_in[0];
    const float4* B = (const float4*)d_in[1];
    float4* O = (float4*)d_out;

    cross_kernel<<<NCTA, TPB>>>(A, B, O);
}

// round 4
// speedup vs baseline: 1.1050x; 1.1050x over previous
#include <cuda_runtime.h>

// Cross product along dim=1 of (16, 3, 1024, 1024) fp32.
// R4: R1 structure (best: 81.4us kernel, DRAM 86.3%) + __ldcs streaming loads
// as the single isolated change. One float4-triple per thread, full grid.

static constexpr int CH_ELEMS  = 1024 * 1024;      // elements per channel plane
static constexpr int CH_VEC    = CH_ELEMS / 4;     // float4 vecs per channel plane
static constexpr int NBATCH    = 16;
static constexpr int TPB       = 256;

__global__ __launch_bounds__(TPB) void cross_kernel(
    const float4* __restrict__ A,
    const float4* __restrict__ B,
    float4* __restrict__ O)
{
    const int s = blockIdx.x * TPB + threadIdx.x;       // spatial vec index [0, CH_VEC)
    const int b = blockIdx.y;                           // batch
    const long base = (long)b * (3L * CH_VEC) + s;

    const float4 a0 = __ldcs(&A[base]);
    const float4 a1 = __ldcs(&A[base + CH_VEC]);
    const float4 a2 = __ldcs(&A[base + 2 * CH_VEC]);
    const float4 b0 = __ldcs(&B[base]);
    const float4 b1 = __ldcs(&B[base + CH_VEC]);
    const float4 b2 = __ldcs(&B[base + 2 * CH_VEC]);

    float4 c0, c1, c2;
    c0.x = fmaf(a1.x, b2.x, -a2.x * b1.x);
    c0.y = fmaf(a1.y, b2.y, -a2.y * b1.y);
    c0.z = fmaf(a1.z, b2.z, -a2.z * b1.z);
    c0.w = fmaf(a1.w, b2.w, -a2.w * b1.w);

    c1.x = fmaf(a2.x, b0.x, -a0.x * b2.x);
    c1.y = fmaf(a2.y, b0.y, -a0.y * b2.y);
    c1.z = fmaf(a2.z, b0.z, -a0.z * b2.z);
    c1.w = fmaf(a2.w, b0.w, -a0.w * b2.w);

    c2.x = fmaf(a0.x, b1.x, -a1.x * b0.x);
    c2.y = fmaf(a0.y, b1.y, -a1.y * b0.y);
    c2.z = fmaf(a0.z, b1.z, -a1.z * b0.z);
    c2.w = fmaf(a0.w, b1.w, -a1.w * b0.w);

    O[base]              = c0;
    O[base + CH_VEC]     = c1;
    O[base + 2 * CH_VEC] = c2;
}

extern "C" void kernel_launch(void* const* d_in, const int* in_sizes, int n_in,
                              void* d_out, int out_size)
{
    const float4* A = (const float4*)d_in[0];
    const float4* B = (const float4*)d_in[1];
    float4* O = (float4*)d_out;

    dim3 grid(CH_VEC / TPB, NBATCH, 1);   // (1024, 16)
    cross_kernel<<<grid, TPB>>>(A, B, O);
}

// round 5
// speedup vs baseline: 1.1183x; 1.0121x over previous
#include <cuda_runtime.h>

// Cross product along dim=1 of (16, 3, 1024, 1024) fp32.
// R5: R1 structure exactly (plain LDG/STG, one float4-triple per thread,
// full 2D grid) with TPB=512 as the single isolated change.

static constexpr int CH_ELEMS  = 1024 * 1024;      // elements per channel plane
static constexpr int CH_VEC    = CH_ELEMS / 4;     // float4 vecs per channel plane
static constexpr int NBATCH    = 16;
static constexpr int TPB       = 512;

__global__ __launch_bounds__(TPB) void cross_kernel(
    const float4* __restrict__ A,
    const float4* __restrict__ B,
    float4* __restrict__ O)
{
    const int s = blockIdx.x * TPB + threadIdx.x;       // spatial vec index [0, CH_VEC)
    const int b = blockIdx.y;                           // batch
    const long base = (long)b * (3L * CH_VEC) + s;

    const float4 a0 = A[base];
    const float4 a1 = A[base + CH_VEC];
    const float4 a2 = A[base + 2 * CH_VEC];
    const float4 b0 = B[base];
    const float4 b1 = B[base + CH_VEC];
    const float4 b2 = B[base + 2 * CH_VEC];

    float4 c0, c1, c2;
    c0.x = fmaf(a1.x, b2.x, -a2.x * b1.x);
    c0.y = fmaf(a1.y, b2.y, -a2.y * b1.y);
    c0.z = fmaf(a1.z, b2.z, -a2.z * b1.z);
    c0.w = fmaf(a1.w, b2.w, -a2.w * b1.w);

    c1.x = fmaf(a2.x, b0.x, -a0.x * b2.x);
    c1.y = fmaf(a2.y, b0.y, -a0.y * b2.y);
    c1.z = fmaf(a2.z, b0.z, -a0.z * b2.z);
    c1.w = fmaf(a2.w, b0.w, -a0.w * b2.w);

    c2.x = fmaf(a0.x, b1.x, -a1.x * b0.x);
    c2.y = fmaf(a0.y, b1.y, -a1.y * b0.y);
    c2.z = fmaf(a0.z, b1.z, -a1.z * b0.z);
    c2.w = fmaf(a0.w, b1.w, -a1.w * b0.w);

    O[base]              = c0;
    O[base + CH_VEC]     = c1;
    O[base + 2 * CH_VEC] = c2;
}

extern "C" void kernel_launch(void* const* d_in, const int* in_sizes, int n_in,
                              void* d_out, int out_size)
{
    const float4* A = (const float4*)d_in[0];
    const float4* B = (const float4*)d_in[1];
    float4* O = (float4*)d_out;

    dim3 grid(CH_VEC / TPB, NBATCH, 1);   // (512, 16)
    cross_kernel<<<grid, TPB>>>(A, B, O);
}

// round 6
// speedup vs baseline: 1.1369x; 1.0166x over previous
#include <cuda_runtime.h>

// Cross product along dim=1 of (16, 3, 1024, 1024) fp32.
// FINAL (R6 = R5 re-verified): one float4-triple per thread, plain LDG/STG,
// full 2D grid, TPB=512. Converged at the DRAM-controller roofline:
// 6.85 TB/s achieved (86% dram_active) on the minimal 576 MiB traffic.
// Falsified alternatives: VPT=2 (+regs, -occ), persistent grid (serialized
// MLP), __ldcs/__stcs (neutral/negative), TPB=256 (tied).

static constexpr int CH_ELEMS  = 1024 * 1024;      // elements per channel plane
static constexpr int CH_VEC    = CH_ELEMS / 4;     // float4 vecs per channel plane
static constexpr int NBATCH    = 16;
static constexpr int TPB       = 512;

__global__ __launch_bounds__(TPB) void cross_kernel(
    const float4* __restrict__ A,
    const float4* __restrict__ B,
    float4* __restrict__ O)
{
    const int s = blockIdx.x * TPB + threadIdx.x;       // spatial vec index [0, CH_VEC)
    const int b = blockIdx.y;                           // batch
    const long base = (long)b * (3L * CH_VEC) + s;

    const float4 a0 = A[base];
    const float4 a1 = A[base + CH_VEC];
    const float4 a2 = A[base + 2 * CH_VEC];
    const float4 b0 = B[base];
    const float4 b1 = B[base + CH_VEC];
    const float4 b2 = B[base + 2 * CH_VEC];

    float4 c0, c1, c2;
    c0.x = fmaf(a1.x, b2.x, -a2.x * b1.x);
    c0.y = fmaf(a1.y, b2.y, -a2.y * b1.y);
    c0.z = fmaf(a1.z, b2.z, -a2.z * b1.z);
    c0.w = fmaf(a1.w, b2.w, -a2.w * b1.w);

    c1.x = fmaf(a2.x, b0.x, -a0.x * b2.x);
    c1.y = fmaf(a2.y, b0.y, -a0.y * b2.y);
    c1.z = fmaf(a2.z, b0.z, -a0.z * b2.z);
    c1.w = fmaf(a2.w, b0.w, -a0.w * b2.w);

    c2.x = fmaf(a0.x, b1.x, -a1.x * b0.x);
    c2.y = fmaf(a0.y, b1.y, -a1.y * b0.y);
    c2.z = fmaf(a0.z, b1.z, -a1.z * b0.z);
    c2.w = fmaf(a0.w, b1.w, -a1.w * b0.w);

    O[base]              = c0;
    O[base + CH_VEC]     = c1;
    O[base + 2 * CH_VEC] = c2;
}

extern "C" void kernel_launch(void* const* d_in, const int* in_sizes, int n_in,
                              void* d_out, int out_size)
{
    const float4* A = (const float4*)d_in[0];
    const float4* B = (const float4*)d_in[1];
    float4* O = (float4*)d_out;

    dim3 grid(CH_VEC / TPB, NBATCH, 1);   // (512, 16)
    cross_kernel<<<grid, TPB>>>(A, B, O);
}